// round 12
// baseline (speedup 1.0000x reference)
#include <cuda_runtime.h>
#include <math.h>

#define TOTAL_NODES 4416   // 2 * 96 * 23
#define NL 96
#define NNN 23
#define DIM 64
#define H1 258
#define AH 260             // padded stride for g_A / g_B (float4-aligned rows)
#define MD 32
#define CH 128
#define THREADS 256

// ---------------- scratch (device globals; no allocs allowed) ----------------
__device__ float g_f[2][TOTAL_NODES * DIM];
__device__ float g_c[2][TOTAL_NODES * 3];
__device__ float g_A[TOTAL_NODES * AH];
__device__ float g_B[TOTAL_NODES * AH];
__device__ float g_mi[TOTAL_NODES * MD];
__device__ float g_delta[TOTAL_NODES * 3];

__device__ __forceinline__ float siluf(float x) {
    return x / (1.0f + __expf(-x));
}

// ---------------- embedding ----------------
__global__ void embed_kernel(const int* __restrict__ tokens,
                             const float* __restrict__ cords,
                             const float* __restrict__ tok_emb,
                             const float* __restrict__ pos_emb) {
    int idx = blockIdx.x * blockDim.x + threadIdx.x;
    if (idx < TOTAL_NODES * DIM) {
        int node = idx / DIM;
        int d = idx - node * DIM;
        int n = node % NNN;
        int bl = node / NNN;
        int t = tokens[bl];
        int pos = (t != 1) ? (n + 2) : 1;
        g_f[0][idx] = tok_emb[t * DIM + d] + pos_emb[pos * DIM + d];
    }
    if (idx < TOTAL_NODES * 3) g_c[0][idx] = cords[idx];
}

// ---------------- per-node precompute: A = f*Wtop + b1, B = f*Wbot ----------------
#define PRE_SM_FLOATS (129 * 260 + 32 * 64)
__global__ void __launch_bounds__(THREADS, 1)
pre_kernel(const float* __restrict__ ew1, const float* __restrict__ eb1,
           int layer, int pin) {
    extern __shared__ float psm[];
    float* sW = psm;                 // [129][260]
    float* sf = psm + 129 * 260;     // [32][64]
    const float* Wg = ew1 + (size_t)layer * 129 * H1;
    int n0 = blockIdx.x * 32;
    for (int idx = threadIdx.x; idx < 129 * H1; idx += THREADS) {
        int k = idx / H1, t = idx - k * H1;
        sW[k * 260 + t] = Wg[idx];
    }
    for (int idx = threadIdx.x; idx < 32 * DIM; idx += THREADS)
        sf[idx] = g_f[pin][n0 * DIM + idx];
    __syncthreads();
    const float* bb = eb1 + layer * H1;
#pragma unroll
    for (int r = 0; r < 8; r++) {
        int idx = threadIdx.x + r * THREADS;      // 0..2047
        int jn = idx >> 6;
        int t0 = (idx & 63) * 4;                  // 0..252
        float4 aA;
        aA.x = bb[t0]; aA.y = bb[t0 + 1]; aA.z = bb[t0 + 2]; aA.w = bb[t0 + 3];
        float4 aB = make_float4(0.f, 0.f, 0.f, 0.f);
        const float* f = &sf[jn * DIM];
        const float* wt = &sW[t0];
        const float* wb = &sW[64 * 260 + t0];
#pragma unroll 4
        for (int k = 0; k < DIM; k++) {
            float fv = f[k];
            float4 t4 = *(const float4*)(wt + k * 260);
            float4 b4 = *(const float4*)(wb + k * 260);
            aA.x += fv * t4.x; aA.y += fv * t4.y; aA.z += fv * t4.z; aA.w += fv * t4.w;
            aB.x += fv * b4.x; aB.y += fv * b4.y; aB.z += fv * b4.z; aB.w += fv * b4.w;
        }
        size_t o = (size_t)(n0 + jn) * AH + t0;
        *(float4*)&g_A[o] = aA;
        *(float4*)&g_B[o] = aB;
    }
    if (threadIdx.x < 64) {                       // tail t = 256, 257
        int jn = threadIdx.x >> 1, t = 256 + (threadIdx.x & 1);
        float aA = bb[t], aB = 0.f;
        const float* f = &sf[jn * DIM];
#pragma unroll 4
        for (int k = 0; k < DIM; k++) {
            float fv = f[k];
            aA += fv * sW[k * 260 + t];
            aB += fv * sW[(64 + k) * 260 + t];
        }
        size_t o = (size_t)(n0 + jn) * AH + t;
        g_A[o] = aA; g_B[o] = aB;
    }
}

// ---------------- fused edge kernel: 23/24-row chunk per block ----------------
#define O_W2   0
#define O_CW1  8256
#define O_WD   12352
#define O_EB2  12612
#define O_CB1  12644
#define O_CW2  12772
#define O_B    12900            // [32][259]
#define O_A    21188            // [24][260]
#define O_H1T  27428            // [258 k][32 j]
#define O_PART 35684            // [4 kc][32 t][32 j]
#define O_M2   39780            // [32 j][33]
#define O_REL  40836            // [32][3]
#define O_DIST 40932
#define O_INV  40964
#define O_WV   40996
#define O_MI   41028            // [24][32]
#define O_DEL  41796            // [24][3]
#define O_CI   41868            // [24][3]
#define O_CJ   41940            // [32][3]
#define EDGE_SM_FLOATS 42048

__global__ void __launch_bounds__(THREADS, 1)
edge_kernel(const float* __restrict__ ew1, const float* __restrict__ ew2,
            const float* __restrict__ eb2, const float* __restrict__ cw1,
            const float* __restrict__ cb1, const float* __restrict__ cw2,
            const float* __restrict__ cb2, int layer, int pin, int phase) {
    extern __shared__ float sm[];
    int tid = threadIdx.x;
    int Nn, TI, base, stride, i0;
    if (phase == 0) {
        Nn = NNN; TI = NNN; base = blockIdx.x * NNN; stride = 1; i0 = 0;
    } else {
        Nn = NL; TI = 24;
        int g2 = blockIdx.x >> 2;
        i0 = (blockIdx.x & 3) * 24;
        int b = g2 / NNN, n = g2 - b * NNN;
        base = b * (NL * NNN) + n;
        stride = NNN;
    }
    // ---- block prologue: weights, A rows, coords, accumulators ----
    {
        const float4* W2g = (const float4*)(ew2 + (size_t)layer * H1 * MD);
        for (int q = tid; q < H1 * MD / 4; q += THREADS) ((float4*)&sm[O_W2])[q] = W2g[q];
        const float4* C1g = (const float4*)(cw1 + (size_t)layer * MD * CH);
        for (int q = tid; q < MD * CH / 4; q += THREADS) ((float4*)&sm[O_CW1])[q] = C1g[q];
        const float* Wdg = ew1 + (size_t)layer * 129 * H1 + (size_t)128 * H1;
        for (int k = tid; k < H1; k += THREADS) sm[O_WD + k] = Wdg[k];
        if (tid < MD) sm[O_EB2 + tid] = eb2[layer * MD + tid];
        if (tid < CH) {
            sm[O_CB1 + tid] = cb1[layer * CH + tid];
            sm[O_CW2 + tid] = cw2[layer * CH + tid];
        }
        for (int idx = tid; idx < TI * H1; idx += THREADS) {
            int i = idx / H1, k = idx - i * H1;
            sm[O_A + i * 260 + k] = g_A[(size_t)(base + (i0 + i) * stride) * AH + k];
        }
        if (tid < TI) {
            int node = base + (i0 + tid) * stride;
            sm[O_CI + tid * 3 + 0] = g_c[pin][node * 3 + 0];
            sm[O_CI + tid * 3 + 1] = g_c[pin][node * 3 + 1];
            sm[O_CI + tid * 3 + 2] = g_c[pin][node * 3 + 2];
        }
        for (int idx = tid; idx < TI * 32; idx += THREADS) sm[O_MI + idx] = 0.f;
        if (tid < TI * 3) sm[O_DEL + tid] = 0.f;
    }
    float cb2v = cb2[layer];
    int jq = tid & 7, tq = (tid >> 3) & 7, kc = tid >> 6;
    int j4 = jq * 4, t4 = tq * 4;
    int k0 = kc * 64, k1 = (kc == 3) ? H1 : (kc * 64 + 64);
    int jh = tid >> 3;            // hc: j index
    int u0 = (tid & 7) * 16;      // hc: 16 u's per thread
    __syncthreads();

    for (int jt = 0; jt < Nn; jt += 32) {
        // ---- stage j-tile: coords + B rows ----
        if (tid < 32 && (jt + tid) < Nn) {
            int node = base + (jt + tid) * stride;
            sm[O_CJ + tid * 3 + 0] = g_c[pin][node * 3 + 0];
            sm[O_CJ + tid * 3 + 1] = g_c[pin][node * 3 + 1];
            sm[O_CJ + tid * 3 + 2] = g_c[pin][node * 3 + 2];
        }
        for (int idx = tid; idx < 32 * H1; idx += THREADS) {
            int j = idx / H1, k = idx - j * H1;
            bool jv = (jt + j) < Nn;
            int node = base + (jt + (jv ? j : 0)) * stride;
            sm[O_B + j * 259 + k] = jv ? g_B[(size_t)node * AH + k] : 0.f;
        }
        __syncthreads();

        for (int i = 0; i < TI; i++) {
            // ---- distances for row i ----
            if (tid < 32) {
                float rx = 0.f, ry = 0.f, rz = 0.f, d = 0.f, inv = 0.f;
                if ((jt + tid) < Nn) {
                    rx = sm[O_CI + i * 3 + 0] - sm[O_CJ + tid * 3 + 0];
                    ry = sm[O_CI + i * 3 + 1] - sm[O_CJ + tid * 3 + 1];
                    rz = sm[O_CI + i * 3 + 2] - sm[O_CJ + tid * 3 + 2];
                    d = rx * rx + ry * ry + rz * rz;
                    inv = 1.0f / fmaxf(sqrtf(d), 1e-8f);
                }
                sm[O_REL + tid * 3 + 0] = rx;
                sm[O_REL + tid * 3 + 1] = ry;
                sm[O_REL + tid * 3 + 2] = rz;
                sm[O_DIST + tid] = d;
                sm[O_INV + tid] = inv;
            }
            __syncthreads();
            // ---- h1 transposed: [k][j] ----
            {
                const float* Ai = &sm[O_A + i * 260];
#pragma unroll 4
                for (int idx = tid; idx < 32 * H1; idx += THREADS) {
                    int k = idx >> 5, j = idx & 31;
                    float v = Ai[k] + sm[O_B + j * 259 + k] + sm[O_DIST + j] * sm[O_WD + k];
                    sm[O_H1T + k * 32 + j] = siluf(v);
                }
            }
            __syncthreads();
            // ---- m2 partial GEMM (4j x 4t per thread, k-split 4) ----
            {
                float a00=0,a01=0,a02=0,a03=0, a10=0,a11=0,a12=0,a13=0;
                float a20=0,a21=0,a22=0,a23=0, a30=0,a31=0,a32=0,a33=0;
#pragma unroll 4
                for (int k = k0; k < k1; k++) {
                    float4 h4 = *(const float4*)&sm[O_H1T + k * 32 + j4];
                    float4 w4 = *(const float4*)&sm[O_W2 + k * 32 + t4];
                    a00 += w4.x*h4.x; a01 += w4.x*h4.y; a02 += w4.x*h4.z; a03 += w4.x*h4.w;
                    a10 += w4.y*h4.x; a11 += w4.y*h4.y; a12 += w4.y*h4.z; a13 += w4.y*h4.w;
                    a20 += w4.z*h4.x; a21 += w4.z*h4.y; a22 += w4.z*h4.z; a23 += w4.z*h4.w;
                    a30 += w4.w*h4.x; a31 += w4.w*h4.y; a32 += w4.w*h4.z; a33 += w4.w*h4.w;
                }
                float* p = &sm[O_PART + kc * 1024 + t4 * 32 + j4];
                *(float4*)(p +  0) = make_float4(a00,a01,a02,a03);
                *(float4*)(p + 32) = make_float4(a10,a11,a12,a13);
                *(float4*)(p + 64) = make_float4(a20,a21,a22,a23);
                *(float4*)(p + 96) = make_float4(a30,a31,a32,a33);
            }
            __syncthreads();
            // ---- reduce partials + bias + silu + mask -> sm2[j][t] ----
#pragma unroll
            for (int r = 0; r < 4; r++) {
                int flat = tid + r * THREADS;     // [t][j]
                int t = flat >> 5, j = flat & 31;
                float v = sm[O_PART + flat] + sm[O_PART + 1024 + flat]
                        + sm[O_PART + 2048 + flat] + sm[O_PART + 3072 + flat]
                        + sm[O_EB2 + t];
                sm[O_M2 + j * 33 + t] = ((jt + j) < Nn) ? siluf(v) : 0.f;
            }
            __syncthreads();
            // ---- hc (register-resident) + w dot, fused ----
            {
                float hc[16];
#pragma unroll
                for (int q = 0; q < 16; q++) hc[q] = 0.f;
                const float* mrow = &sm[O_M2 + jh * 33];
#pragma unroll 4
                for (int t = 0; t < 32; t++) {
                    float m = mrow[t];
                    const float* wr = &sm[O_CW1 + t * CH + u0];
                    float4 w0 = *(const float4*)(wr + 0);
                    float4 w1 = *(const float4*)(wr + 4);
                    float4 w2 = *(const float4*)(wr + 8);
                    float4 w3 = *(const float4*)(wr + 12);
                    hc[0]+=m*w0.x; hc[1]+=m*w0.y; hc[2]+=m*w0.z; hc[3]+=m*w0.w;
                    hc[4]+=m*w1.x; hc[5]+=m*w1.y; hc[6]+=m*w1.z; hc[7]+=m*w1.w;
                    hc[8]+=m*w2.x; hc[9]+=m*w2.y; hc[10]+=m*w2.z; hc[11]+=m*w2.w;
                    hc[12]+=m*w3.x; hc[13]+=m*w3.y; hc[14]+=m*w3.z; hc[15]+=m*w3.w;
                }
                float p = 0.f;
#pragma unroll
                for (int q = 0; q < 16; q++)
                    p += siluf(hc[q] + sm[O_CB1 + u0 + q]) * sm[O_CW2 + u0 + q];
                p += __shfl_xor_sync(0xffffffffu, p, 4);
                p += __shfl_xor_sync(0xffffffffu, p, 2);
                p += __shfl_xor_sync(0xffffffffu, p, 1);
                if ((tid & 7) == 0)
                    sm[O_WV + jh] = ((jt + jh) < Nn) ? (p + cb2v) : 0.f;
            }
            __syncthreads();
            // ---- accumulate m_i and delta for row i ----
            if (tid < 32) {
                float acc = 0.f;
#pragma unroll
                for (int j = 0; j < 32; j++) acc += sm[O_M2 + j * 33 + tid];
                sm[O_MI + i * 32 + tid] += acc;
            } else if (tid < 35) {
                int c = tid - 32;
                float acc = 0.f;
#pragma unroll
                for (int j = 0; j < 32; j++)
                    acc += sm[O_WV + j] * sm[O_REL + j * 3 + c] * sm[O_INV + j];
                sm[O_DEL + i * 3 + c] += acc;
            }
            __syncthreads();
        } // row i
    } // jt

    // ---- final writes ----
    for (int idx = tid; idx < TI * 32; idx += THREADS) {
        int i = idx >> 5, t = idx & 31;
        g_mi[(size_t)(base + (i0 + i) * stride) * MD + t] = sm[O_MI + idx];
    }
    if (tid < TI * 3) {
        int i = tid / 3, c = tid - 3 * i;
        g_delta[(base + (i0 + i) * stride) * 3 + c] = sm[O_DEL + tid];
    }
}

// ---------------- node update + coord update (32 nodes / block) ----------------
#define NODE_SM_FLOATS (12288 + 8192 + 3072 + 4096)
__global__ void __launch_bounds__(THREADS, 1)
node_kernel(const float* __restrict__ nw1, const float* __restrict__ nb1,
            const float* __restrict__ nw2, const float* __restrict__ nb2,
            const float* __restrict__ ln_b, int layer, int pin) {
    extern __shared__ float nsm[];
    float* sW1  = nsm;              // [96][128]
    float* sW2  = nsm + 12288;      // [128][64]
    float* sin_ = nsm + 20480;      // [32][96]
    float* sh   = nsm + 23552;      // [32][128]
    int tid = threadIdx.x;
    int n0 = blockIdx.x * 32;
    int pout = pin ^ 1;
    const float4* W1g = (const float4*)(nw1 + (size_t)layer * 96 * 128);
    for (int q = tid; q < 3072; q += THREADS) ((float4*)sW1)[q] = W1g[q];
    const float4* W2g = (const float4*)(nw2 + (size_t)layer * 128 * 64);
    for (int q = tid; q < 2048; q += THREADS) ((float4*)sW2)[q] = W2g[q];
    for (int idx = tid; idx < 32 * 96; idx += THREADS) {
        int jn = idx / 96, k = idx - jn * 96;
        sin_[idx] = (k < DIM) ? g_f[pin][(n0 + jn) * DIM + k]
                              : g_mi[(size_t)(n0 + jn) * MD + (k - DIM)];
    }
    __syncthreads();
    const float* b1 = nb1 + layer * 128;
#pragma unroll
    for (int r = 0; r < 4; r++) {
        int idx = tid + r * THREADS;        // 0..1023
        int jn = idx >> 5, uq = idx & 31;
        float4 a = *(const float4*)&b1[uq * 4];
        const float* f = &sin_[jn * 96];
        const float* wp = &sW1[uq * 4];
#pragma unroll 4
        for (int k = 0; k < 96; k++) {
            float fv = f[k];
            float4 w4 = *(const float4*)(wp + k * 128);
            a.x += fv * w4.x; a.y += fv * w4.y; a.z += fv * w4.z; a.w += fv * w4.w;
        }
        a.x = siluf(a.x); a.y = siluf(a.y); a.z = siluf(a.z); a.w = siluf(a.w);
        *(float4*)&sh[jn * 128 + uq * 4] = a;
    }
    __syncthreads();
    const float* b2 = nb2 + layer * 64;
#pragma unroll
    for (int r = 0; r < 2; r++) {
        int idx = tid + r * THREADS;        // 0..511
        int jn = idx >> 4, dq = idx & 15;
        float4 a = *(const float4*)&b2[dq * 4];
        const float* hh = &sh[jn * 128];
        const float* wp = &sW2[dq * 4];
#pragma unroll 4
        for (int k = 0; k < 128; k++) {
            float hv = hh[k];
            float4 w4 = *(const float4*)(wp + k * 64);
            a.x += hv * w4.x; a.y += hv * w4.y; a.z += hv * w4.z; a.w += hv * w4.w;
        }
        float4 res = *(const float4*)&sin_[jn * 96 + dq * 4];
        a.x += res.x; a.y += res.y; a.z += res.z; a.w += res.w;
        *(float4*)&g_f[pout][(n0 + jn) * DIM + dq * 4] = a;
    }
    float scale = ln_b[layer] * (1.0f / 50.0f);
    if (tid < 96)
        g_c[pout][n0 * 3 + tid] = g_c[pin][n0 * 3 + tid] + scale * g_delta[n0 * 3 + tid];
}

// ---------------- final copy ----------------
__global__ void copy_out_kernel(float* __restrict__ out) {
    int idx = blockIdx.x * blockDim.x + threadIdx.x;
    if (idx < TOTAL_NODES * 3) out[idx] = g_c[0][idx];
}

extern "C" void kernel_launch(void* const* d_in, const int* in_sizes, int n_in,
                              void* d_out, int out_size) {
    const int*   tokens  = (const int*)  d_in[0];
    const float* cords   = (const float*)d_in[1];
    const float* tok_emb = (const float*)d_in[2];
    const float* pos_emb = (const float*)d_in[3];
    const float* ew1 = (const float*)d_in[4];
    const float* eb1 = (const float*)d_in[5];
    const float* ew2 = (const float*)d_in[6];
    const float* eb2 = (const float*)d_in[7];
    const float* cw1 = (const float*)d_in[8];
    const float* cb1 = (const float*)d_in[9];
    const float* cw2 = (const float*)d_in[10];
    const float* cb2 = (const float*)d_in[11];
    const float* nw1 = (const float*)d_in[12];
    const float* nb1 = (const float*)d_in[13];
    const float* nw2 = (const float*)d_in[14];
    const float* nb2 = (const float*)d_in[15];
    const float* ln_b = (const float*)d_in[17];
    float* out = (float*)d_out;

    cudaFuncSetAttribute(pre_kernel, cudaFuncAttributeMaxDynamicSharedMemorySize,
                         PRE_SM_FLOATS * (int)sizeof(float));
    cudaFuncSetAttribute(edge_kernel, cudaFuncAttributeMaxDynamicSharedMemorySize,
                         EDGE_SM_FLOATS * (int)sizeof(float));
    cudaFuncSetAttribute(node_kernel, cudaFuncAttributeMaxDynamicSharedMemorySize,
                         NODE_SM_FLOATS * (int)sizeof(float));

    embed_kernel<<<(TOTAL_NODES * DIM + THREADS - 1) / THREADS, THREADS>>>(
        tokens, cords, tok_emb, pos_emb);

    int pin = 0;
    for (int L = 0; L < 16; L++) {
        int phase = (L >> 2) & 1;
        int egrid = (phase == 0) ? 192 : 184;   // 192 graphs x 23 | 46 graphs x 4 chunks
        pre_kernel<<<TOTAL_NODES / 32, THREADS, PRE_SM_FLOATS * (int)sizeof(float)>>>(
            ew1, eb1, L, pin);
        edge_kernel<<<egrid, THREADS, EDGE_SM_FLOATS * (int)sizeof(float)>>>(
            ew1, ew2, eb2, cw1, cb1, cw2, cb2, L, pin, phase);
        node_kernel<<<TOTAL_NODES / 32, THREADS, NODE_SM_FLOATS * (int)sizeof(float)>>>(
            nw1, nb1, nw2, nb2, ln_b, L, pin);
        pin ^= 1;
    }
    copy_out_kernel<<<(TOTAL_NODES * 3 + THREADS - 1) / THREADS, THREADS>>>(out);
}

// round 14
// speedup vs baseline: 1.5270x; 1.5270x over previous
#include <cuda_runtime.h>
#include <math.h>

#define TOTAL_NODES 4416   // 2 * 96 * 23
#define NL 96
#define NNN 23
#define DIM 64
#define H1 258
#define AH 260             // padded stride for g_A / g_B
#define MD 32
#define CH 128
#define THREADS 256

// ---------------- scratch (device globals; no allocs allowed) ----------------
__device__ float g_f[2][TOTAL_NODES * DIM];
__device__ float g_c[2][TOTAL_NODES * 3];
__device__ float g_A[TOTAL_NODES * AH];
__device__ float g_B[TOTAL_NODES * AH];
__device__ float g_mi[TOTAL_NODES * MD];
__device__ float g_delta[TOTAL_NODES * 3];

__device__ __forceinline__ float siluf(float x) {
    return __fdividef(x, 1.0f + __expf(-x));
}

// ---------------- embedding ----------------
__global__ void embed_kernel(const int* __restrict__ tokens,
                             const float* __restrict__ cords,
                             const float* __restrict__ tok_emb,
                             const float* __restrict__ pos_emb) {
    int idx = blockIdx.x * blockDim.x + threadIdx.x;
    if (idx < TOTAL_NODES * DIM) {
        int node = idx / DIM;
        int d = idx - node * DIM;
        int n = node % NNN;
        int bl = node / NNN;
        int t = tokens[bl];
        int pos = (t != 1) ? (n + 2) : 1;
        g_f[0][idx] = tok_emb[t * DIM + d] + pos_emb[pos * DIM + d];
    }
    if (idx < TOTAL_NODES * 3) g_c[0][idx] = cords[idx];
}

// ---------------- per-node precompute: A = f*Wtop + b1, B = f*Wbot ----------------
#define PRE_SM_FLOATS (129 * 260 + 32 * 64)
__global__ void __launch_bounds__(THREADS, 1)
pre_kernel(const float* __restrict__ ew1, const float* __restrict__ eb1,
           int layer, int pin) {
    extern __shared__ float psm[];
    float* sW = psm;                 // [129][260]
    float* sf = psm + 129 * 260;     // [32][64]
    const float* Wg = ew1 + (size_t)layer * 129 * H1;
    int n0 = blockIdx.x * 32;
    for (int idx = threadIdx.x; idx < 129 * H1; idx += THREADS) {
        int k = idx / H1, t = idx - k * H1;
        sW[k * 260 + t] = Wg[idx];
    }
    for (int idx = threadIdx.x; idx < 32 * DIM; idx += THREADS)
        sf[idx] = g_f[pin][n0 * DIM + idx];
    __syncthreads();
    const float* bb = eb1 + layer * H1;
#pragma unroll
    for (int r = 0; r < 8; r++) {
        int idx = threadIdx.x + r * THREADS;
        int jn = idx >> 6;
        int t0 = (idx & 63) * 4;
        float4 aA;
        aA.x = bb[t0]; aA.y = bb[t0 + 1]; aA.z = bb[t0 + 2]; aA.w = bb[t0 + 3];
        float4 aB = make_float4(0.f, 0.f, 0.f, 0.f);
        const float* f = &sf[jn * DIM];
        const float* wt = &sW[t0];
        const float* wb = &sW[64 * 260 + t0];
#pragma unroll 4
        for (int k = 0; k < DIM; k++) {
            float fv = f[k];
            float4 t4 = *(const float4*)(wt + k * 260);
            float4 b4 = *(const float4*)(wb + k * 260);
            aA.x += fv * t4.x; aA.y += fv * t4.y; aA.z += fv * t4.z; aA.w += fv * t4.w;
            aB.x += fv * b4.x; aB.y += fv * b4.y; aB.z += fv * b4.z; aB.w += fv * b4.w;
        }
        size_t o = (size_t)(n0 + jn) * AH + t0;
        *(float4*)&g_A[o] = aA;
        *(float4*)&g_B[o] = aB;
    }
    if (threadIdx.x < 64) {
        int jn = threadIdx.x >> 1, t = 256 + (threadIdx.x & 1);
        float aA = bb[t], aB = 0.f;
        const float* f = &sf[jn * DIM];
#pragma unroll 4
        for (int k = 0; k < DIM; k++) {
            float fv = f[k];
            aA += fv * sW[k * 260 + t];
            aB += fv * sW[(64 + k) * 260 + t];
        }
        size_t o = (size_t)(n0 + jn) * AH + t;
        g_A[o] = aA; g_B[o] = aB;
    }
}

// ---------------- fused edge kernel: edge-batched GEMM over (i,j) pairs ----------------
#define O_W2   0            // [258 k][32 t]
#define O_CW1  8256         // [32 k][128 u]
#define O_WD   12352        // 260
#define O_EB2  12612        // 32
#define O_CB1  12644        // 128
#define O_CW2  12772        // 128
#define O_B    12900        // [32 j][259]
#define O_A    21188        // [32 i][260]
#define O_H1   29508        // [32 k][256 e]
#define O_M2   37700        // [256 e][33]
#define O_REL  46148        // [256 e][3]
#define O_DIST 46916        // [256]
#define O_INV  47172        // [256]
#define O_WV   47428        // [256]
#define O_MI   47684        // [32 i][32 t]
#define O_DEL  48708        // [32 i][3]
#define O_CI   48804        // [32 i][3]
#define O_CJ   48900        // [32 j][3]
#define EDGE_SM_FLOATS 48996

__global__ void __launch_bounds__(THREADS, 1)
edge_kernel(const float* __restrict__ ew1, const float* __restrict__ ew2,
            const float* __restrict__ eb2, const float* __restrict__ cw1,
            const float* __restrict__ cb1, const float* __restrict__ cw2,
            const float* __restrict__ cb2, int layer, int pin, int phase) {
    extern __shared__ float sm[];
    int tid = threadIdx.x;
    int Nn, TI, base, stride, i0, njt, nsub;
    if (phase == 0) {
        Nn = NNN; TI = NNN; base = blockIdx.x * NNN; stride = 1;
        i0 = 0; njt = 1; nsub = 3;                      // TIP = 24 (last i padded)
    } else {
        Nn = NL; TI = 32;
        int g2 = blockIdx.x / 3;
        i0 = (blockIdx.x - g2 * 3) * 32;
        int b = g2 / NNN, n = g2 - b * NNN;
        base = b * (NL * NNN) + n; stride = NNN;
        njt = 3; nsub = 4;                              // TIP = 32
    }
    int TIP = nsub * 8;

    // ---- prologue: weights, A rows, coords, accumulators ----
    {
        const float4* W2g = (const float4*)(ew2 + (size_t)layer * H1 * MD);
        for (int q = tid; q < H1 * MD / 4; q += THREADS) ((float4*)&sm[O_W2])[q] = W2g[q];
        const float4* C1g = (const float4*)(cw1 + (size_t)layer * MD * CH);
        for (int q = tid; q < MD * CH / 4; q += THREADS) ((float4*)&sm[O_CW1])[q] = C1g[q];
        const float* Wdg = ew1 + (size_t)layer * 129 * H1 + (size_t)128 * H1;
        for (int k = tid; k < H1; k += THREADS) sm[O_WD + k] = Wdg[k];
        if (tid < MD) sm[O_EB2 + tid] = eb2[layer * MD + tid];
        if (tid < CH) {
            sm[O_CB1 + tid] = cb1[layer * CH + tid];
            sm[O_CW2 + tid] = cw2[layer * CH + tid];
        }
        for (int idx = tid; idx < TIP * H1; idx += THREADS) {
            int i = idx / H1, k = idx - i * H1;
            int im = min(i, TI - 1);
            sm[O_A + i * 260 + k] = g_A[(size_t)(base + (i0 + im) * stride) * AH + k];
        }
        if (tid < TIP) {
            int im = min(tid, TI - 1);
            int node = base + (i0 + im) * stride;
            sm[O_CI + tid * 3 + 0] = g_c[pin][node * 3 + 0];
            sm[O_CI + tid * 3 + 1] = g_c[pin][node * 3 + 1];
            sm[O_CI + tid * 3 + 2] = g_c[pin][node * 3 + 2];
        }
        for (int idx = tid; idx < TIP * 32; idx += THREADS) sm[O_MI + idx] = 0.f;
        if (tid < TIP * 3) sm[O_DEL + tid] = 0.f;
    }
    float cb2v = cb2[layer];
    int e0 = (tid & 31) * 8;       // GEMM: 8 edges
    int t0 = (tid >> 5) * 4;       // GEMM: 4 t's
    int wrp = tid >> 5, lane = tid & 31;
    int le = lane >> 3, lu = lane & 7, u0 = lu * 16;

    for (int jt = 0; jt < njt; jt++) {
        __syncthreads();
        if (tid < 32) {
            int jj = min(jt * 32 + tid, Nn - 1);
            int node = base + jj * stride;
            sm[O_CJ + tid * 3 + 0] = g_c[pin][node * 3 + 0];
            sm[O_CJ + tid * 3 + 1] = g_c[pin][node * 3 + 1];
            sm[O_CJ + tid * 3 + 2] = g_c[pin][node * 3 + 2];
        }
        for (int idx = tid; idx < 32 * H1; idx += THREADS) {
            int j = idx / H1, k = idx - j * H1;
            int jj = min(jt * 32 + j, Nn - 1);
            sm[O_B + j * 259 + k] = g_B[(size_t)(base + jj * stride) * AH + k];
        }
        __syncthreads();

        for (int s = 0; s < nsub; s++) {
            // ---- per-edge geometry (thread owns edge e = tid) ----
            int il = s * 8 + (tid >> 5);
            int jj = tid & 31;
            float rx = sm[O_CI + il * 3 + 0] - sm[O_CJ + jj * 3 + 0];
            float ry = sm[O_CI + il * 3 + 1] - sm[O_CJ + jj * 3 + 1];
            float rz = sm[O_CI + il * 3 + 2] - sm[O_CJ + jj * 3 + 2];
            float dreg = rx * rx + ry * ry + rz * rz;
            sm[O_REL + tid * 3 + 0] = rx;
            sm[O_REL + tid * 3 + 1] = ry;
            sm[O_REL + tid * 3 + 2] = rz;
            sm[O_DIST + tid] = dreg;
            sm[O_INV + tid] = __frcp_rn(fmaxf(sqrtf(dreg), 1e-8f));

            const float* Ai = &sm[O_A + il * 260];
            const float* Bj = &sm[O_B + jj * 259];

            // ---- m2 GEMM accumulators ----
            float acc[8][4];
#pragma unroll
            for (int ee = 0; ee < 8; ee++) {
                acc[ee][0] = sm[O_EB2 + t0 + 0];
                acc[ee][1] = sm[O_EB2 + t0 + 1];
                acc[ee][2] = sm[O_EB2 + t0 + 2];
                acc[ee][3] = sm[O_EB2 + t0 + 3];
            }
            // ---- k-chunks of 32 (8 chunks) ----
            for (int kc = 0; kc < 8; kc++) {
                int K0 = kc * 32;
                __syncthreads();   // h1 buffer free (prev chunk GEMM done)
#pragma unroll 8
                for (int r = 0; r < 32; r++) {
                    float v = Ai[K0 + r] + Bj[K0 + r] + dreg * sm[O_WD + K0 + r];
                    sm[O_H1 + r * 256 + tid] = siluf(v);
                }
                __syncthreads();
#pragma unroll 8
                for (int k = 0; k < 32; k++) {
                    float4 w4 = *(const float4*)&sm[O_W2 + (K0 + k) * 32 + t0];
                    float4 ha = *(const float4*)&sm[O_H1 + k * 256 + e0];
                    float4 hb = *(const float4*)&sm[O_H1 + k * 256 + e0 + 4];
                    float h[8];
                    h[0]=ha.x; h[1]=ha.y; h[2]=ha.z; h[3]=ha.w;
                    h[4]=hb.x; h[5]=hb.y; h[6]=hb.z; h[7]=hb.w;
#pragma unroll
                    for (int ee = 0; ee < 8; ee++) {
                        acc[ee][0] += h[ee] * w4.x;
                        acc[ee][1] += h[ee] * w4.y;
                        acc[ee][2] += h[ee] * w4.z;
                        acc[ee][3] += h[ee] * w4.w;
                    }
                }
            }
            // ---- k tail (256, 257) ----
            __syncthreads();
            {
                float v0 = Ai[256] + Bj[256] + dreg * sm[O_WD + 256];
                float v1 = Ai[257] + Bj[257] + dreg * sm[O_WD + 257];
                sm[O_H1 + 0 * 256 + tid] = siluf(v0);
                sm[O_H1 + 1 * 256 + tid] = siluf(v1);
            }
            __syncthreads();
#pragma unroll
            for (int k = 0; k < 2; k++) {
                float4 w4 = *(const float4*)&sm[O_W2 + (256 + k) * 32 + t0];
                float4 ha = *(const float4*)&sm[O_H1 + k * 256 + e0];
                float4 hb = *(const float4*)&sm[O_H1 + k * 256 + e0 + 4];
                float h[8];
                h[0]=ha.x; h[1]=ha.y; h[2]=ha.z; h[3]=ha.w;
                h[4]=hb.x; h[5]=hb.y; h[6]=hb.z; h[7]=hb.w;
#pragma unroll
                for (int ee = 0; ee < 8; ee++) {
                    acc[ee][0] += h[ee] * w4.x;
                    acc[ee][1] += h[ee] * w4.y;
                    acc[ee][2] += h[ee] * w4.z;
                    acc[ee][3] += h[ee] * w4.w;
                }
            }
            // ---- write m2 (silu + j mask) ----
#pragma unroll
            for (int ee = 0; ee < 8; ee++) {
                int e = e0 + ee;
                bool jv = (jt * 32 + (e & 31)) < Nn;
                float* mrow = &sm[O_M2 + e * 33 + t0];
                mrow[0] = jv ? siluf(acc[ee][0]) : 0.f;
                mrow[1] = jv ? siluf(acc[ee][1]) : 0.f;
                mrow[2] = jv ? siluf(acc[ee][2]) : 0.f;
                mrow[3] = jv ? siluf(acc[ee][3]) : 0.f;
            }
            __syncthreads();

            // ---- hc GEMM + w dot (8 passes; warp = 4 edges, 8 lanes/edge, 16 u/lane) ----
            for (int p = 0; p < 8; p++) {
                int e = p * 32 + wrp * 4 + le;
                float hcv[16];
#pragma unroll
                for (int q = 0; q < 16; q++) hcv[q] = 0.f;
                const float* mrow = &sm[O_M2 + e * 33];
#pragma unroll 4
                for (int k = 0; k < 32; k++) {
                    float m = mrow[k];
                    const float* wr = &sm[O_CW1 + k * CH + u0];
                    float4 w0 = *(const float4*)(wr + 0);
                    float4 w1 = *(const float4*)(wr + 4);
                    float4 w2 = *(const float4*)(wr + 8);
                    float4 w3 = *(const float4*)(wr + 12);
                    hcv[0]+=m*w0.x; hcv[1]+=m*w0.y; hcv[2]+=m*w0.z; hcv[3]+=m*w0.w;
                    hcv[4]+=m*w1.x; hcv[5]+=m*w1.y; hcv[6]+=m*w1.z; hcv[7]+=m*w1.w;
                    hcv[8]+=m*w2.x; hcv[9]+=m*w2.y; hcv[10]+=m*w2.z; hcv[11]+=m*w2.w;
                    hcv[12]+=m*w3.x; hcv[13]+=m*w3.y; hcv[14]+=m*w3.z; hcv[15]+=m*w3.w;
                }
                float pv = 0.f;
#pragma unroll
                for (int q = 0; q < 16; q++)
                    pv += siluf(hcv[q] + sm[O_CB1 + u0 + q]) * sm[O_CW2 + u0 + q];
                pv += __shfl_xor_sync(0xffffffffu, pv, 1);
                pv += __shfl_xor_sync(0xffffffffu, pv, 2);
                pv += __shfl_xor_sync(0xffffffffu, pv, 4);
                if (lu == 0) {
                    int j2 = e & 31;
                    sm[O_WV + e] = ((jt * 32 + j2) < Nn) ? (pv + cb2v) : 0.f;
                }
            }
            __syncthreads();

            // ---- accumulate m_i (all threads) ----
            {
                int is = tid >> 5, t = tid & 31;
                float a = 0.f;
#pragma unroll
                for (int j = 0; j < 32; j++) a += sm[O_M2 + (is * 32 + j) * 33 + t];
                sm[O_MI + (s * 8 + is) * 32 + t] += a;
            }
            // ---- accumulate delta (24 threads) ----
            if (tid < 24) {
                int is = tid / 3, c = tid - 3 * is;
                float a = 0.f;
#pragma unroll
                for (int j = 0; j < 32; j++) {
                    int e = is * 32 + j;
                    a += sm[O_WV + e] * sm[O_REL + e * 3 + c] * sm[O_INV + e];
                }
                sm[O_DEL + (s * 8 + is) * 3 + c] += a;
            }
            __syncthreads();
        } // subtiles
    } // j-tiles

    // ---- final writes ----
    for (int idx = tid; idx < TIP * 32; idx += THREADS) {
        int i = idx >> 5, t = idx & 31;
        if (i < TI)
            g_mi[(size_t)(base + (i0 + i) * stride) * MD + t] = sm[O_MI + idx];
    }
    if (tid < TIP * 3) {
        int i = tid / 3, c = tid - 3 * i;
        if (i < TI)
            g_delta[(base + (i0 + i) * stride) * 3 + c] = sm[O_DEL + tid];
    }
}

// ---------------- node update + coord update (32 nodes / block) ----------------
#define NODE_SM_FLOATS (12288 + 8192 + 3072 + 4096)
__global__ void __launch_bounds__(THREADS, 1)
node_kernel(const float* __restrict__ nw1, const float* __restrict__ nb1,
            const float* __restrict__ nw2, const float* __restrict__ nb2,
            const float* __restrict__ ln_b, int layer, int pin) {
    extern __shared__ float nsm[];
    float* sW1  = nsm;              // [96][128]
    float* sW2  = nsm + 12288;      // [128][64]
    float* sin_ = nsm + 20480;      // [32][96]
    float* sh   = nsm + 23552;      // [32][128]
    int tid = threadIdx.x;
    int n0 = blockIdx.x * 32;
    int pout = pin ^ 1;
    const float4* W1g = (const float4*)(nw1 + (size_t)layer * 96 * 128);
    for (int q = tid; q < 3072; q += THREADS) ((float4*)sW1)[q] = W1g[q];
    const float4* W2g = (const float4*)(nw2 + (size_t)layer * 128 * 64);
    for (int q = tid; q < 2048; q += THREADS) ((float4*)sW2)[q] = W2g[q];
    for (int idx = tid; idx < 32 * 96; idx += THREADS) {
        int jn = idx / 96, k = idx - jn * 96;
        sin_[idx] = (k < DIM) ? g_f[pin][(n0 + jn) * DIM + k]
                              : g_mi[(size_t)(n0 + jn) * MD + (k - DIM)];
    }
    __syncthreads();
    const float* b1 = nb1 + layer * 128;
#pragma unroll
    for (int r = 0; r < 4; r++) {
        int idx = tid + r * THREADS;
        int jn = idx >> 5, uq = idx & 31;
        float4 a = *(const float4*)&b1[uq * 4];
        const float* f = &sin_[jn * 96];
        const float* wp = &sW1[uq * 4];
#pragma unroll 4
        for (int k = 0; k < 96; k++) {
            float fv = f[k];
            float4 w4 = *(const float4*)(wp + k * 128);
            a.x += fv * w4.x; a.y += fv * w4.y; a.z += fv * w4.z; a.w += fv * w4.w;
        }
        a.x = siluf(a.x); a.y = siluf(a.y); a.z = siluf(a.z); a.w = siluf(a.w);
        *(float4*)&sh[jn * 128 + uq * 4] = a;
    }
    __syncthreads();
    const float* b2 = nb2 + layer * 64;
#pragma unroll
    for (int r = 0; r < 2; r++) {
        int idx = tid + r * THREADS;
        int jn = idx >> 4, dq = idx & 15;
        float4 a = *(const float4*)&b2[dq * 4];
        const float* hh = &sh[jn * 128];
        const float* wp = &sW2[dq * 4];
#pragma unroll 4
        for (int k = 0; k < 128; k++) {
            float hv = hh[k];
            float4 w4 = *(const float4*)(wp + k * 64);
            a.x += hv * w4.x; a.y += hv * w4.y; a.z += hv * w4.z; a.w += hv * w4.w;
        }
        float4 res = *(const float4*)&sin_[jn * 96 + dq * 4];
        a.x += res.x; a.y += res.y; a.z += res.z; a.w += res.w;
        *(float4*)&g_f[pout][(n0 + jn) * DIM + dq * 4] = a;
    }
    float scale = ln_b[layer] * (1.0f / 50.0f);
    if (tid < 96)
        g_c[pout][n0 * 3 + tid] = g_c[pin][n0 * 3 + tid] + scale * g_delta[n0 * 3 + tid];
}

// ---------------- final copy ----------------
__global__ void copy_out_kernel(float* __restrict__ out) {
    int idx = blockIdx.x * blockDim.x + threadIdx.x;
    if (idx < TOTAL_NODES * 3) out[idx] = g_c[0][idx];
}

extern "C" void kernel_launch(void* const* d_in, const int* in_sizes, int n_in,
                              void* d_out, int out_size) {
    const int*   tokens  = (const int*)  d_in[0];
    const float* cords   = (const float*)d_in[1];
    const float* tok_emb = (const float*)d_in[2];
    const float* pos_emb = (const float*)d_in[3];
    const float* ew1 = (const float*)d_in[4];
    const float* eb1 = (const float*)d_in[5];
    const float* ew2 = (const float*)d_in[6];
    const float* eb2 = (const float*)d_in[7];
    const float* cw1 = (const float*)d_in[8];
    const float* cb1 = (const float*)d_in[9];
    const float* cw2 = (const float*)d_in[10];
    const float* cb2 = (const float*)d_in[11];
    const float* nw1 = (const float*)d_in[12];
    const float* nb1 = (const float*)d_in[13];
    const float* nw2 = (const float*)d_in[14];
    const float* nb2 = (const float*)d_in[15];
    const float* ln_b = (const float*)d_in[17];
    float* out = (float*)d_out;

    cudaFuncSetAttribute(pre_kernel, cudaFuncAttributeMaxDynamicSharedMemorySize,
                         PRE_SM_FLOATS * (int)sizeof(float));
    cudaFuncSetAttribute(edge_kernel, cudaFuncAttributeMaxDynamicSharedMemorySize,
                         EDGE_SM_FLOATS * (int)sizeof(float));
    cudaFuncSetAttribute(node_kernel, cudaFuncAttributeMaxDynamicSharedMemorySize,
                         NODE_SM_FLOATS * (int)sizeof(float));

    embed_kernel<<<(TOTAL_NODES * DIM + THREADS - 1) / THREADS, THREADS>>>(
        tokens, cords, tok_emb, pos_emb);

    int pin = 0;
    for (int L = 0; L < 16; L++) {
        int phase = (L >> 2) & 1;
        int egrid = (phase == 0) ? 192 : 138;   // 192 graphs | 46 graphs x 3 i-chunks
        pre_kernel<<<TOTAL_NODES / 32, THREADS, PRE_SM_FLOATS * (int)sizeof(float)>>>(
            ew1, eb1, L, pin);
        edge_kernel<<<egrid, THREADS, EDGE_SM_FLOATS * (int)sizeof(float)>>>(
            ew1, ew2, eb2, cw1, cb1, cw2, cb2, L, pin, phase);
        node_kernel<<<TOTAL_NODES / 32, THREADS, NODE_SM_FLOATS * (int)sizeof(float)>>>(
            nw1, nb1, nw2, nb2, ln_b, L, pin);
        pin ^= 1;
    }
    copy_out_kernel<<<(TOTAL_NODES * 3 + THREADS - 1) / THREADS, THREADS>>>(out);
}